// round 13
// baseline (speedup 1.0000x reference)
#include <cuda_runtime.h>
#include <cuda_fp16.h>
#include <cuda_bf16.h>

// Problem shapes (fixed by the dataset):
//   text:        [16, 2048, 256] f32      d_in[0]
//   const_mat:   [16, 2048, 2048] i32     d_in[1]   (UNUSED: softmax rows sum to 1)
//   const_labels:[16, 2048, 8] i32        d_in[2]
//   emb_table:   [100, 128] f32           d_in[3]
//   attn_W:      [256, 384] f32           d_in[4]   (UNUSED: cancels in softmax)
//   attn_b:      [256] f32                d_in[5]   (UNUSED)
//   fc_W:        [256, 128] f32           d_in[6]
//   fc_b:        [256] f32                d_in[7]
//   out:         [16, 2048, 256] f32
//
// Collapse: out[pos,d] = relu( text[pos,d] + sum_{k=0..7} G[labels[pos,k], d] )
// with G[n,d] = 0.125 * (fc_b[d] + emb_table[n] . fc_W[d]), G stored fp16.
//
// R13: SINGLE kernel. CTAs 0..99 build one G row each and publish through an
// atomic ready-counter; every CTA preloads its text/labels into registers
// BEFORE spinning on the counter, so the build latency hides under the text
// DRAM prologue. Counters self-reset at kernel end (graph-replay clean,
// deterministic). Eliminates the ~5us build_G node + launch gap measured
// every round since R1. Gathers use plain loads (g_Gh written this launch --
// stay off the read-only NC path).

#define CN    100
#define CD    128
#define DIM   256
#define KLBL  8
#define NCTA  4096
#define NTHR  256

__device__ __half g_Gh[CN * DIM];   // 50 KB fp16 table
__device__ int    g_ready = 0;      // rows published
__device__ int    g_fini  = 0;      // CTAs finished (for reset)

__device__ __forceinline__ __half2 as_h2(unsigned u) {
    return *reinterpret_cast<const __half2*>(&u);
}

// ld.global.lu float4: last-use in L1, default L2 (text read once per replay,
// must stay L2-resident across replays).
__device__ __forceinline__ float4 ldlu_f4(const float4* p) {
    float4 v;
    asm volatile("ld.global.lu.v4.f32 {%0,%1,%2,%3}, [%4];"
                 : "=f"(v.x), "=f"(v.y), "=f"(v.z), "=f"(v.w)
                 : "l"(p));
    return v;
}

__device__ __forceinline__ float4 reduce8(
    const uint2& u0, const uint2& u1, const uint2& u2, const uint2& u3,
    const uint2& u4, const uint2& u5, const uint2& u6, const uint2& u7,
    const float4& t)
{
    const __half2 p0lo = __hadd2(as_h2(u0.x), as_h2(u1.x));
    const __half2 p0hi = __hadd2(as_h2(u0.y), as_h2(u1.y));
    const __half2 p1lo = __hadd2(as_h2(u2.x), as_h2(u3.x));
    const __half2 p1hi = __hadd2(as_h2(u2.y), as_h2(u3.y));
    const __half2 p2lo = __hadd2(as_h2(u4.x), as_h2(u5.x));
    const __half2 p2hi = __hadd2(as_h2(u4.y), as_h2(u5.y));
    const __half2 p3lo = __hadd2(as_h2(u6.x), as_h2(u7.x));
    const __half2 p3hi = __hadd2(as_h2(u6.y), as_h2(u7.y));

    const float2 f0lo = __half22float2(p0lo);
    const float2 f1lo = __half22float2(p1lo);
    const float2 f2lo = __half22float2(p2lo);
    const float2 f3lo = __half22float2(p3lo);
    const float2 f0hi = __half22float2(p0hi);
    const float2 f1hi = __half22float2(p1hi);
    const float2 f2hi = __half22float2(p2hi);
    const float2 f3hi = __half22float2(p3hi);

    float4 r;
    r.x = fmaxf(t.x + (f0lo.x + f1lo.x) + (f2lo.x + f3lo.x), 0.0f);
    r.y = fmaxf(t.y + (f0lo.y + f1lo.y) + (f2lo.y + f3lo.y), 0.0f);
    r.z = fmaxf(t.z + (f0hi.x + f1hi.x) + (f2hi.x + f3hi.x), 0.0f);
    r.w = fmaxf(t.w + (f0hi.y + f1hi.y) + (f2hi.y + f3hi.y), 0.0f);
    return r;
}

// Gather + finish for one (pos, d4) pair of float4s. Plain loads on g_Gh.
__device__ __forceinline__ void gather_and_store(
    int idxA, int d4, const int4& l0, const int4& l1,
    const float4& tA, const float4& tB, float4* __restrict__ out4)
{
    const uint2* Gh = reinterpret_cast<const uint2*>(g_Gh);

    const int b0 = (l0.x << 6) + d4;
    const int b1 = (l0.y << 6) + d4;
    const int b2 = (l0.z << 6) + d4;
    const int b3 = (l0.w << 6) + d4;
    const int b4 = (l1.x << 6) + d4;
    const int b5 = (l1.y << 6) + d4;
    const int b6 = (l1.z << 6) + d4;
    const int b7 = (l1.w << 6) + d4;

    const uint2 a0 = Gh[b0];
    const uint2 a1 = Gh[b1];
    const uint2 a2 = Gh[b2];
    const uint2 a3 = Gh[b3];
    const uint2 a4 = Gh[b4];
    const uint2 a5 = Gh[b5];
    const uint2 a6 = Gh[b6];
    const uint2 a7 = Gh[b7];

    const uint2 c0 = Gh[b0 + 32];
    const uint2 c1 = Gh[b1 + 32];
    const uint2 c2 = Gh[b2 + 32];
    const uint2 c3 = Gh[b3 + 32];
    const uint2 c4 = Gh[b4 + 32];
    const uint2 c5 = Gh[b5 + 32];
    const uint2 c6 = Gh[b6 + 32];
    const uint2 c7 = Gh[b7 + 32];

    const float4 rA = reduce8(a0, a1, a2, a3, a4, a5, a6, a7, tA);
    const float4 rB = reduce8(c0, c1, c2, c3, c4, c5, c6, c7, tB);

    __stcs(out4 + idxA, rA);
    __stcs(out4 + idxA + 32, rB);
}

__global__ void __launch_bounds__(NTHR, 5) fused_all_kernel(
    const float4* __restrict__ text4,
    const int*    __restrict__ labels,
    const float*  __restrict__ emb_table,
    const float*  __restrict__ fc_W,
    const float*  __restrict__ fc_b,
    float*        __restrict__ out4_raw)
{
    float4* out4 = reinterpret_cast<float4*>(out4_raw);
    const int tid = threadIdx.x;
    const int bid = blockIdx.x;
    const int gid = bid * NTHR + tid;

    const int pos = gid >> 5;   // warp-uniform
    const int d4  = gid & 31;
    const int idxA = (pos << 6) + d4;

    if (bid < CN) {
        // ---- Builder CTA: compute G row `bid`, publish, then do own share.
        __shared__ float se[CD];
        if (tid < CD) se[tid] = emb_table[bid * CD + tid];
        __syncthreads();

        const float4* w4 = reinterpret_cast<const float4*>(fc_W + tid * CD);
        float acc = fc_b[tid];
        #pragma unroll
        for (int c4 = 0; c4 < CD / 4; c4++) {
            float4 w = __ldg(w4 + c4);
            acc = fmaf(se[c4 * 4 + 0], w.x, acc);
            acc = fmaf(se[c4 * 4 + 1], w.y, acc);
            acc = fmaf(se[c4 * 4 + 2], w.z, acc);
            acc = fmaf(se[c4 * 4 + 3], w.w, acc);
        }
        g_Gh[bid * DIM + tid] = __float2half_rn(0.125f * acc);

        __threadfence();          // publish row to L2
        __syncthreads();          // all 256 stores done
        if (tid == 0) atomicAdd(&g_ready, 1);

        // Wait for all rows, then process this CTA's fused share.
        if (tid == 0) {
            while (*(volatile int*)&g_ready < CN) __nanosleep(60);
        }
        __syncthreads();
        __threadfence();          // acquire

        const int4* lb = reinterpret_cast<const int4*>(labels) + (pos << 1);
        const int4 l0 = __ldg(lb + 0);
        const int4 l1 = __ldg(lb + 1);
        const float4 tA = ldlu_f4(text4 + idxA);
        const float4 tB = ldlu_f4(text4 + idxA + 32);
        gather_and_store(idxA, d4, l0, l1, tA, tB, out4);
    } else {
        // ---- Waiter CTA: preload text/labels (independent of G), then spin.
        const int4* lb = reinterpret_cast<const int4*>(labels) + (pos << 1);
        const int4 l0 = __ldg(lb + 0);
        const int4 l1 = __ldg(lb + 1);
        const float4 tA = ldlu_f4(text4 + idxA);
        const float4 tB = ldlu_f4(text4 + idxA + 32);

        if (tid == 0) {
            while (*(volatile int*)&g_ready < CN) __nanosleep(60);
        }
        __syncthreads();
        __threadfence();          // acquire: order gathers after flag

        gather_and_store(idxA, d4, l0, l1, tA, tB, out4);
    }

    // ---- Self-reset for the next graph replay (deterministic).
    if (tid == 0) {
        const int old = atomicAdd(&g_fini, 1);
        if (old == NCTA - 1) {
            g_fini = 0;
            __threadfence();
            g_ready = 0;
        }
    }
}

// ---------------------------------------------------------------------------
extern "C" void kernel_launch(void* const* d_in, const int* in_sizes, int n_in,
                              void* d_out, int out_size)
{
    const float* text      = (const float*)d_in[0];
    const int*   labels    = (const int*)  d_in[2];
    const float* emb_table = (const float*)d_in[3];
    const float* fc_W      = (const float*)d_in[6];
    const float* fc_b      = (const float*)d_in[7];
    float*       out       = (float*)d_out;

    // ntotal = 8,388,608 -> 1,048,576 threads -> 4096 CTAs of 256 exactly.
    fused_all_kernel<<<NCTA, NTHR>>>(
        reinterpret_cast<const float4*>(text),
        labels, emb_table, fc_W, fc_b, out);
}

// round 14
// speedup vs baseline: 1.4654x; 1.4654x over previous
#include <cuda_runtime.h>
#include <cuda_fp16.h>
#include <cuda_bf16.h>

// Problem shapes (fixed by the dataset):
//   text:        [16, 2048, 256] f32      d_in[0]
//   const_mat:   [16, 2048, 2048] i32     d_in[1]   (UNUSED: softmax rows sum to 1)
//   const_labels:[16, 2048, 8] i32        d_in[2]
//   emb_table:   [100, 128] f32           d_in[3]
//   attn_W:      [256, 384] f32           d_in[4]   (UNUSED: cancels in softmax)
//   attn_b:      [256] f32                d_in[5]   (UNUSED)
//   fc_W:        [256, 128] f32           d_in[6]
//   fc_b:        [256] f32                d_in[7]
//   out:         [16, 2048, 256] f32
//
// Collapse: out[pos,d] = relu( text[pos,d] + sum_{k=0..7} G[labels[pos,k], d] )
// with G[n,d] = 0.125 * (fc_b[d] + emb_table[n] . fc_W[d]), G stored fp16.
//
// R14 = R12 fused kernel (13.9us, converged) + COALESCED build_G.
// Old build_G had thread d reading fc_W[d*128+c]: adjacent lanes 512B apart,
// 32 lines per LDG = ~8k wavefronts/CTA at 100 CTAs ~= 4-5us. That was the
// whole "launch gap" measured since R1. New build: warp owns (n,d), lanes
// cover c (coalesced float4), shfl_xor reduce. 32x fewer wavefronts.

#define CN    100
#define CD    128
#define DIM   256
#define KLBL  8

__device__ __half g_Gh[CN * DIM];  // 50 KB fp16 table

// ---------------------------------------------------------------------------
// Kernel A: G[n,d] = 0.125 * (fc_b[d] + sum_c emb_table[n,c] * fc_W[d,c])
// grid = (CN, 4), block = 256. Warp computes one (n,d) per iteration, lanes
// spanning c. All fc_W traffic coalesced.
// ---------------------------------------------------------------------------
__global__ void __launch_bounds__(256) build_G_kernel(
    const float* __restrict__ emb_table,
    const float* __restrict__ fc_W,
    const float* __restrict__ fc_b)
{
    const int n   = blockIdx.x;
    const int tid = threadIdx.x;

    __shared__ float4 se4[CD / 4];   // emb row n as float4
    if (tid < CD / 4)
        se4[tid] = reinterpret_cast<const float4*>(emb_table + n * CD)[tid];
    __syncthreads();

    const int warp = tid >> 5;
    const int lane = tid & 31;
    const float4 e = se4[lane];      // lane's c-chunk (conflict-free LDS)

    const float4* W4 = reinterpret_cast<const float4*>(fc_W);

    #pragma unroll
    for (int i = 0; i < 8; i++) {
        const int d = (blockIdx.y << 6) + (i << 3) + warp;   // 0..255

        // Coalesced: lane reads fc_W[d, 4*lane .. 4*lane+3].
        const float4 w = __ldg(W4 + d * 32 + lane);
        float p = w.x * e.x + w.y * e.y + w.z * e.z + w.w * e.w;

        p += __shfl_xor_sync(0xFFFFFFFFu, p, 16);
        p += __shfl_xor_sync(0xFFFFFFFFu, p, 8);
        p += __shfl_xor_sync(0xFFFFFFFFu, p, 4);
        p += __shfl_xor_sync(0xFFFFFFFFu, p, 2);
        p += __shfl_xor_sync(0xFFFFFFFFu, p, 1);

        if (lane == 0)
            g_Gh[n * DIM + d] = __float2half_rn(0.125f * (p + __ldg(fc_b + d)));
    }
}

// ---------------------------------------------------------------------------
// Kernel B: fused gather-add-relu (identical to R12 best).
// ---------------------------------------------------------------------------
__device__ __forceinline__ __half2 as_h2(unsigned u) {
    return *reinterpret_cast<const __half2*>(&u);
}

// ld.global.lu float4: last-use in L1 (evict-first locally), default L2.
__device__ __forceinline__ float4 ldlu_f4(const float4* p) {
    float4 v;
    asm volatile("ld.global.lu.v4.f32 {%0,%1,%2,%3}, [%4];"
                 : "=f"(v.x), "=f"(v.y), "=f"(v.z), "=f"(v.w)
                 : "l"(p));
    return v;
}

__device__ __forceinline__ float4 reduce8(
    const uint2& u0, const uint2& u1, const uint2& u2, const uint2& u3,
    const uint2& u4, const uint2& u5, const uint2& u6, const uint2& u7,
    const float4& t)
{
    const __half2 p0lo = __hadd2(as_h2(u0.x), as_h2(u1.x));
    const __half2 p0hi = __hadd2(as_h2(u0.y), as_h2(u1.y));
    const __half2 p1lo = __hadd2(as_h2(u2.x), as_h2(u3.x));
    const __half2 p1hi = __hadd2(as_h2(u2.y), as_h2(u3.y));
    const __half2 p2lo = __hadd2(as_h2(u4.x), as_h2(u5.x));
    const __half2 p2hi = __hadd2(as_h2(u4.y), as_h2(u5.y));
    const __half2 p3lo = __hadd2(as_h2(u6.x), as_h2(u7.x));
    const __half2 p3hi = __hadd2(as_h2(u6.y), as_h2(u7.y));

    const float2 f0lo = __half22float2(p0lo);
    const float2 f1lo = __half22float2(p1lo);
    const float2 f2lo = __half22float2(p2lo);
    const float2 f3lo = __half22float2(p3lo);
    const float2 f0hi = __half22float2(p0hi);
    const float2 f1hi = __half22float2(p1hi);
    const float2 f2hi = __half22float2(p2hi);
    const float2 f3hi = __half22float2(p3hi);

    float4 r;
    r.x = fmaxf(t.x + (f0lo.x + f1lo.x) + (f2lo.x + f3lo.x), 0.0f);
    r.y = fmaxf(t.y + (f0lo.y + f1lo.y) + (f2lo.y + f3lo.y), 0.0f);
    r.z = fmaxf(t.z + (f0hi.x + f1hi.x) + (f2hi.x + f3hi.x), 0.0f);
    r.w = fmaxf(t.w + (f0hi.y + f1hi.y) + (f2hi.y + f3hi.y), 0.0f);
    return r;
}

__global__ void __launch_bounds__(256, 6) fused_gather_kernel(
    const float4* __restrict__ text4,
    const int*    __restrict__ labels,
    float4*       __restrict__ out4)
{
    const int gid = blockIdx.x * blockDim.x + threadIdx.x;   // exact grid

    const int pos = gid >> 5;        // warp-uniform (warp = one position)
    const int d4  = gid & 31;        // uint2 slot 0..31; twin at d4+32

    const int4* lb = reinterpret_cast<const int4*>(labels) + (pos << 1);
    const int4 l0 = __ldg(lb + 0);
    const int4 l1 = __ldg(lb + 1);

    const uint2* __restrict__ Gh = reinterpret_cast<const uint2*>(g_Gh);

    const int idxA = (pos << 6) + d4;        // output float4 index, low half
    const int idxB = idxA + 32;              // high half

    const float4 tA = ldlu_f4(text4 + idxA);
    const float4 tB = ldlu_f4(text4 + idxB);

    const int b0 = (l0.x << 6) + d4;
    const int b1 = (l0.y << 6) + d4;
    const int b2 = (l0.z << 6) + d4;
    const int b3 = (l0.w << 6) + d4;
    const int b4 = (l1.x << 6) + d4;
    const int b5 = (l1.y << 6) + d4;
    const int b6 = (l1.z << 6) + d4;
    const int b7 = (l1.w << 6) + d4;

    const uint2 a0 = __ldg(Gh + b0);
    const uint2 a1 = __ldg(Gh + b1);
    const uint2 a2 = __ldg(Gh + b2);
    const uint2 a3 = __ldg(Gh + b3);
    const uint2 a4 = __ldg(Gh + b4);
    const uint2 a5 = __ldg(Gh + b5);
    const uint2 a6 = __ldg(Gh + b6);
    const uint2 a7 = __ldg(Gh + b7);

    const uint2 c0 = __ldg(Gh + b0 + 32);
    const uint2 c1 = __ldg(Gh + b1 + 32);
    const uint2 c2 = __ldg(Gh + b2 + 32);
    const uint2 c3 = __ldg(Gh + b3 + 32);
    const uint2 c4 = __ldg(Gh + b4 + 32);
    const uint2 c5 = __ldg(Gh + b5 + 32);
    const uint2 c6 = __ldg(Gh + b6 + 32);
    const uint2 c7 = __ldg(Gh + b7 + 32);

    const float4 rA = reduce8(a0, a1, a2, a3, a4, a5, a6, a7, tA);
    const float4 rB = reduce8(c0, c1, c2, c3, c4, c5, c6, c7, tB);

    __stcs(out4 + idxA, rA);
    __stcs(out4 + idxB, rB);
}

// ---------------------------------------------------------------------------
extern "C" void kernel_launch(void* const* d_in, const int* in_sizes, int n_in,
                              void* d_out, int out_size)
{
    const float* text      = (const float*)d_in[0];
    const int*   labels    = (const int*)  d_in[2];
    const float* emb_table = (const float*)d_in[3];
    const float* fc_W      = (const float*)d_in[6];
    const float* fc_b      = (const float*)d_in[7];
    float*       out       = (float*)d_out;

    const int ntotal = in_sizes[0];        // 8,388,608
    const int nhalf  = ntotal / 8;         // 1,048,576 threads (2 float4 each)

    build_G_kernel<<<dim3(CN, 4), 256>>>(emb_table, fc_W, fc_b);

    const int block = 256;
    const int grid  = nhalf / block;       // 4096 exactly
    fused_gather_kernel<<<grid, block>>>(
        reinterpret_cast<const float4*>(text),
        labels,
        reinterpret_cast<float4*>(out));
}